// round 9
// baseline (speedup 1.0000x reference)
#include <cuda_runtime.h>
#include <math.h>

// Depthwise 5x5 Gaussian blur, separable, software-pipelined over planes.
// float4 carriers: each thread owns a 4-row x 4-col tile (LDG.128/STG.128,
// 1 shuffle per element). Horizontal pass via 16-lane-segment shuffles,
// vertical pass via a full-row ping-pong smem exchange (1 barrier/plane).
// x: [16, 256, 64, 64] f32, sigma: [1] f32. PPB=4 planes per 256-thread block.

#define HH 64
#define WW 64
#define TPB 256
#define PPB 4

__global__ __launch_bounds__(TPB, 4) void gauss5_kernel(const float* __restrict__ x,
                                                        const float* __restrict__ sigma_p,
                                                        float* __restrict__ out)
{
    // ping-pong horizontal-result buffers: 68 rows (2 zero-halo rows each side)
    // x 16 float4 columns. Data rows 2..65.
    __shared__ float4 sbuf[2][68][16];   // 34 KB

    const int tid = threadIdx.x;
    const int rb  = tid >> 4;         // 4-row group index (0..15)
    const int qc  = tid & 15;         // float4 column group (0..15)

    const long plane0 = (long)blockIdx.x * PPB;
    const float4* gin  = reinterpret_cast<const float4*>(x)   + plane0 * 1024;
    float4*       gout = reinterpret_cast<float4*>(out)       + plane0 * 1024;

    // Gaussian taps (symmetric), center tap folded to 1; normalize at the end.
    const float sigma = sigma_p[0];
    const float inv2s2 = 1.0f / (2.0f * sigma * sigma);
    const float g0 = expf(-4.0f * inv2s2);   // |d| = 2
    const float g1 = expf(-1.0f * inv2s2);   // |d| = 1
    const float s1 = 2.0f * (g0 + g1) + 1.0f;
    const float invn = 1.0f / (s1 * s1);

    // zero halo rows in BOTH buffers (rows 0,1,66,67; never overwritten)
    if (tid < 128) {
        int buf = tid >> 6;           // 0/1
        int idx = tid & 63;
        int hr  = idx >> 4;           // 0..3
        int c   = idx & 15;
        int row = (hr < 2) ? hr : (hr + 64);
        sbuf[buf][row][c] = make_float4(0.f, 0.f, 0.f, 0.f);
    }

    const int base = (rb << 2) * 16 + qc;   // float4 index of (row rb*4, colgroup qc)

    // preload plane 0
    float4 cur[4];
    #pragma unroll
    for (int j = 0; j < 4; j++) cur[j] = gin[base + j * 16];

    #pragma unroll
    for (int p = 0; p < PPB; p++) {
        // issue next plane's loads early (independent of current compute)
        float4 nxt[4];
        if (p + 1 < PPB) {
            #pragma unroll
            for (int j = 0; j < 4; j++) nxt[j] = gin[(p + 1) * 1024 + base + j * 16];
        }

        // --- horizontal pass (registers + 16-lane-segment shuffles) ---
        float4 t[4];
        float4 (*sp)[16] = sbuf[p & 1];
        #pragma unroll
        for (int j = 0; j < 4; j++) {
            float4 b = cur[j];
            float pz = __shfl_up_sync(0xffffffffu, b.z, 1, 16);   // col 4c-2
            float pw = __shfl_up_sync(0xffffffffu, b.w, 1, 16);   // col 4c-1
            float nx = __shfl_down_sync(0xffffffffu, b.x, 1, 16); // col 4c+4
            float ny = __shfl_down_sync(0xffffffffu, b.y, 1, 16); // col 4c+5
            if (qc == 0)  { pz = 0.0f; pw = 0.0f; }               // left zero-pad
            if (qc == 15) { nx = 0.0f; ny = 0.0f; }               // right zero-pad
            t[j].x = g0 * (pz + b.z) + g1 * (pw + b.y) + b.x;
            t[j].y = g0 * (pw + b.w) + g1 * (b.x + b.z) + b.y;
            t[j].z = g0 * (b.x + nx) + g1 * (b.y + b.w) + b.z;
            t[j].w = g0 * (b.y + ny) + g1 * (b.z + nx) + b.w;
            sp[(rb << 2) + 2 + j][qc] = t[j];    // share row immediately
        }
        __syncthreads();

        // --- halo rows from smem (padded rows 4rb,4rb+1,4rb+6,4rb+7) ---
        float4 w[8];
        w[0] = sp[(rb << 2) + 0][qc];   // real row 4rb-2
        w[1] = sp[(rb << 2) + 1][qc];   // real row 4rb-1
        w[2] = t[0]; w[3] = t[1]; w[4] = t[2]; w[5] = t[3];
        w[6] = sp[(rb << 2) + 6][qc];   // real row 4rb+4
        w[7] = sp[(rb << 2) + 7][qc];   // real row 4rb+5

        // --- vertical pass + streaming 128-bit stores ---
        float4* go = gout + p * 1024 + base;
        #pragma unroll
        for (int j = 0; j < 4; j++) {
            float4 o;
            o.x = (g0 * (w[j].x + w[j+4].x) + g1 * (w[j+1].x + w[j+3].x) + w[j+2].x) * invn;
            o.y = (g0 * (w[j].y + w[j+4].y) + g1 * (w[j+1].y + w[j+3].y) + w[j+2].y) * invn;
            o.z = (g0 * (w[j].z + w[j+4].z) + g1 * (w[j+1].z + w[j+3].z) + w[j+2].z) * invn;
            o.w = (g0 * (w[j].w + w[j+4].w) + g1 * (w[j+1].w + w[j+3].w) + w[j+2].w) * invn;
            __stcs(go + j * 16, o);
        }

        // rotate pipeline
        if (p + 1 < PPB) {
            #pragma unroll
            for (int j = 0; j < 4; j++) cur[j] = nxt[j];
        }
    }
}

extern "C" void kernel_launch(void* const* d_in, const int* in_sizes, int n_in,
                              void* d_out, int out_size) {
    const float* x = (const float*)d_in[0];
    const float* sigma = (const float*)d_in[1];
    float* out = (float*)d_out;
    int planes = in_sizes[0] / (HH * WW);   // 4096
    gauss5_kernel<<<planes / PPB, TPB>>>(x, sigma, out);
}

// round 10
// speedup vs baseline: 1.1304x; 1.1304x over previous
#include <cuda_runtime.h>
#include <math.h>

// Depthwise 5x5 Gaussian blur, separable, barrier-free column streaming.
// One warp = one 32-row x 64-col half-plane strip; lane owns 2 columns.
// Vertical pass first (pure per-thread rolling window over rows), then
// horizontal on the vertical sum via +-1 lane shuffles. No smem, no syncs.
// x: [16, 256, 64, 64] f32, sigma: [1] f32.

#define HH 64
#define WW 64
#define TPB 256
#define PD  4            // prefetch distance in rows

__global__ __launch_bounds__(TPB) void gauss5_kernel(const float* __restrict__ x,
                                                     const float* __restrict__ sigma_p,
                                                     float* __restrict__ out)
{
    const int tid  = threadIdx.x;
    const int lane = tid & 31;                       // column pair (cols 2l, 2l+1)
    const int gw   = blockIdx.x * (TPB / 32) + (tid >> 5);
    const int plane = gw >> 1;                       // 0..4095
    const int half  = gw & 1;                        // strip: rows 0-31 or 32-63

    const float2* gin  = reinterpret_cast<const float2*>(x)   + (long)plane * 2048;
    float2*       gout = reinterpret_cast<float2*>(out)       + (long)plane * 2048
                                                              + half * 32 * 32;

    // Gaussian taps (symmetric), center tap folded to 1.
    const float sigma = sigma_p[0];
    const float inv2s2 = 1.0f / (2.0f * sigma * sigma);
    const float g0 = expf(-4.0f * inv2s2);   // |d| = 2
    const float g1 = expf(-1.0f * inv2s2);   // |d| = 1
    const float s1 = 2.0f * (g0 + g1) + 1.0f;
    const float invn = 1.0f / (s1 * s1);
    // fold normalization into the vertical stage
    const float vg0 = g0 * invn;
    const float vg1 = g1 * invn;
    const float vg2 = invn;

    const int row0 = half * 32 - 2;          // input row held by in[0]

    // fully unrolled software pipeline: in[j] holds input row row0+j
    float2 in[36];

    #pragma unroll
    for (int j = 0; j < 5 + PD; j++) {
        int r = row0 + j;
        in[j] = (r >= 0 && r < HH) ? gin[r * 32 + lane] : make_float2(0.f, 0.f);
    }

    #pragma unroll
    for (int rr = 0; rr < 32; rr++) {
        // prefetch row rr + 5 + PD
        if (rr + 5 + PD < 36) {
            int r = row0 + rr + 5 + PD;
            in[rr + 5 + PD] = (r >= 0 && r < HH) ? gin[r * 32 + lane]
                                                 : make_float2(0.f, 0.f);
        }

        // vertical pass on rows rr..rr+4 (normalization folded in)
        float2 v;
        v.x = vg0 * (in[rr].x + in[rr+4].x) + vg1 * (in[rr+1].x + in[rr+3].x)
            + vg2 * in[rr+2].x;
        v.y = vg0 * (in[rr].y + in[rr+4].y) + vg1 * (in[rr+1].y + in[rr+3].y)
            + vg2 * in[rr+2].y;

        // horizontal pass on the vertical sum (in-warp shuffles)
        float px = __shfl_up_sync(0xffffffffu, v.x, 1);    // col 2l-2
        float py = __shfl_up_sync(0xffffffffu, v.y, 1);    // col 2l-1
        float nx = __shfl_down_sync(0xffffffffu, v.x, 1);  // col 2l+2
        float ny = __shfl_down_sync(0xffffffffu, v.y, 1);  // col 2l+3
        if (lane == 0)  { px = 0.0f; py = 0.0f; }          // left zero-pad
        if (lane == 31) { nx = 0.0f; ny = 0.0f; }          // right zero-pad

        float2 o;
        o.x = g0 * (px + nx) + g1 * (py + v.y) + v.x;
        o.y = g0 * (py + ny) + g1 * (v.x + nx) + v.y;
        __stcs(gout + rr * 32 + lane, o);
    }
}

extern "C" void kernel_launch(void* const* d_in, const int* in_sizes, int n_in,
                              void* d_out, int out_size) {
    const float* x = (const float*)d_in[0];
    const float* sigma = (const float*)d_in[1];
    float* out = (float*)d_out;
    int planes = in_sizes[0] / (HH * WW);            // 4096
    int warps  = planes * 2;                         // half-plane strips
    gauss5_kernel<<<warps / (TPB / 32), TPB>>>(x, sigma, out);
}